// round 13
// baseline (speedup 1.0000x reference)
#include <cuda_runtime.h>
#include <cuda_fp16.h>
#include <math_constants.h>
#include <cstdint>

#define DIN  256
#define DOUT 128
#define NMAX 100000
#define EMAX 3200000
#define ALPHA 0.2f
#define WCONV_BLOCKS 128

// ---- scratch (static device globals; no allocation) ----
__device__ __half  g_seqh[(size_t)NMAX * DOUT]; // seq_fts (fp16 storage)
__device__ __half  g_Wh[DOUT * DIN];            // W transposed [n][k], fp16
__device__ float   g_f1[NMAX];
__device__ float   g_f2[NMAX];
__device__ int     g_cnt[NMAX];                 // zero at call entry (self-cleaning)
__device__ int     g_off[NMAX];
__device__ int     g_cur[NMAX];
__device__ int     g_bsum[512];
__device__ int     g_ecol[EMAX];

// ---------------------------------------------------------------------------
// combo1: blocks [0,128)   -> W transpose + fp16 convert
//         blocks [128,...) -> edge pass 1: per-row edge count (x4)
__global__ void k_combo1(const float* __restrict__ W,
                         const int* __restrict__ row, int e) {
    if (blockIdx.x < WCONV_BLOCKS) {
        int idx = blockIdx.x * blockDim.x + threadIdx.x;   // 0..32767
        int nn = idx >> 8;
        int kk = idx & 255;
        g_Wh[idx] = __float2half_rn(W[kk * DOUT + nn]);
    } else {
        int bi = blockIdx.x - WCONV_BLOCKS;
        int i = (bi * blockDim.x + threadIdx.x) * 4;
        if (i + 4 <= e) {
            int4 r4 = *(const int4*)(row + i);
            atomicAdd(&g_cnt[r4.x], 1);
            atomicAdd(&g_cnt[r4.y], 1);
            atomicAdd(&g_cnt[r4.z], 1);
            atomicAdd(&g_cnt[r4.w], 1);
        } else {
            for (int k = i; k < e; k++) atomicAdd(&g_cnt[row[k]], 1);
        }
    }
}

// ---------------------------------------------------------------------------
// scan1: block-local exclusive scan of g_cnt -> g_off; resets g_cnt.
__global__ void k_scan1(int n) {
    __shared__ int sh[256];
    int t = threadIdx.x;
    int i = blockIdx.x * 256 + t;
    int v = (i < n) ? g_cnt[i] : 0;
    sh[t] = v;
    __syncthreads();
    #pragma unroll
    for (int o = 1; o < 256; o <<= 1) {
        int x = (t >= o) ? sh[t - o] : 0;
        __syncthreads();
        sh[t] += x;
        __syncthreads();
    }
    if (i < n) { g_off[i] = sh[t] - v; g_cnt[i] = 0; }
    if (t == 255) g_bsum[blockIdx.x] = sh[255];
}

// scan23: every block redundantly scans the block sums, adds prefix.
__global__ void k_scan23(int n, int nblk) {
    __shared__ int sh[512];
    int t = threadIdx.x;
    int v = (t < nblk) ? g_bsum[t] : 0;
    sh[t] = v;
    __syncthreads();
    #pragma unroll
    for (int o = 1; o < 512; o <<= 1) {
        int x = (t >= o) ? sh[t - o] : 0;
        __syncthreads();
        sh[t] += x;
        __syncthreads();
    }
    int ex = sh[t] - v;
    __syncthreads();
    sh[t] = ex;
    __syncthreads();
    int i = blockIdx.x * 512 + t;
    if (i < n) {
        int o = g_off[i] + sh[i >> 8];
        g_off[i] = o;
        g_cur[i] = o;
    }
}

// ---------------------------------------------------------------------------
// combo2: blocks [0,GB)  -> fp16 HMMA GEMM (64x128 tile) + f1/f2 epilogue
//         blocks [GB,..) -> edge pass 2 (CSR scatter of col, x4)
// 64-row tile: acc 32 regs -> ~85 regs total -> 3 CTAs/SM.
#define HSTR 40
__global__ __launch_bounds__(256, 3) void k_combo2(const float* __restrict__ A,
                                                   const float* __restrict__ al_w,
                                                   const float* __restrict__ al_b,
                                                   const float* __restrict__ ar_w,
                                                   const float* __restrict__ ar_b,
                                                   const int* __restrict__ row,
                                                   const int* __restrict__ col,
                                                   int n, int e, int GB) {
    if (blockIdx.x >= GB) {
        int bi = blockIdx.x - GB;
        int i = (bi * blockDim.x + threadIdx.x) * 4;
        if (i + 4 <= e) {
            int4 r4 = *(const int4*)(row + i);
            int4 c4 = *(const int4*)(col + i);
            int p0 = atomicAdd(&g_cur[r4.x], 1);
            int p1 = atomicAdd(&g_cur[r4.y], 1);
            int p2 = atomicAdd(&g_cur[r4.z], 1);
            int p3 = atomicAdd(&g_cur[r4.w], 1);
            g_ecol[p0] = c4.x; g_ecol[p1] = c4.y;
            g_ecol[p2] = c4.z; g_ecol[p3] = c4.w;
        } else {
            for (int k = i; k < e; k++) {
                int p = atomicAdd(&g_cur[row[k]], 1);
                g_ecol[p] = col[k];
            }
        }
        return;
    }

    // ---------------- GEMM: 64 rows x 128 cols per block ----------------
    __shared__ __half As[64 * HSTR];    // [m][k], k contiguous
    __shared__ __half Bs[128 * HSTR];   // [n][k], k contiguous

    int tid  = threadIdx.x;
    int wid  = tid >> 5;
    int lane = tid & 31;
    int warp_m = wid & 3;               // 0..3 -> 16 rows each
    int warp_n = wid >> 2;              // 0..1 -> 64 cols each
    int group  = lane >> 2;             // 0..7
    int tig    = lane & 3;              // 0..3
    int rowBase = blockIdx.x * 64;

    float acc[8][4];
    #pragma unroll
    for (int nt = 0; nt < 8; nt++)
        #pragma unroll
        for (int q = 0; q < 4; q++) acc[nt][q] = 0.0f;

    for (int k0 = 0; k0 < DIN; k0 += 32) {
        // stage A: 64 rows x 32 k fp32 -> fp16. 512 float4; 2 per thread.
        #pragma unroll
        for (int i = 0; i < 2; i++) {
            int idx = tid + 256 * i;         // 0..511
            int m   = idx >> 3;              // 0..63
            int q   = idx & 7;
            int gr  = rowBase + m;
            float4 v = make_float4(0.f, 0.f, 0.f, 0.f);
            if (gr < n) v = *(const float4*)(A + (size_t)gr * DIN + k0 + q * 4);
            __half2 h0 = __floats2half2_rn(v.x, v.y);
            __half2 h1 = __floats2half2_rn(v.z, v.w);
            uint2 u;
            u.x = *reinterpret_cast<uint32_t*>(&h0);
            u.y = *reinterpret_cast<uint32_t*>(&h1);
            *(uint2*)&As[m * HSTR + q * 4] = u;
        }
        // stage B: 128 n-rows x 32 k halves. 512 uint4; 2 per thread.
        #pragma unroll
        for (int i = 0; i < 2; i++) {
            int idx = tid + 256 * i;
            int nn  = idx >> 2;
            int q   = idx & 3;
            *(uint4*)&Bs[nn * HSTR + q * 8] =
                *(const uint4*)(g_Wh + nn * DIN + k0 + q * 8);
        }
        __syncthreads();

        #pragma unroll
        for (int ks = 0; ks < 2; ks++) {
            int kb = ks * 16;
            uint32_t af[4];
            {
                int m = warp_m * 16 + group;
                const __half* pr0 = &As[m * HSTR + kb + tig * 2];
                const __half* pr1 = &As[(m + 8) * HSTR + kb + tig * 2];
                af[0] = *(const uint32_t*)(pr0);
                af[1] = *(const uint32_t*)(pr1);
                af[2] = *(const uint32_t*)(pr0 + 8);
                af[3] = *(const uint32_t*)(pr1 + 8);
            }
            uint32_t bf[8][2];
            #pragma unroll
            for (int nt = 0; nt < 8; nt++) {
                int nn = warp_n * 64 + nt * 8 + group;
                const __half* pb = &Bs[nn * HSTR + kb + tig * 2];
                bf[nt][0] = *(const uint32_t*)(pb);
                bf[nt][1] = *(const uint32_t*)(pb + 8);
            }
            #pragma unroll
            for (int nt = 0; nt < 8; nt++) {
                asm volatile(
                    "mma.sync.aligned.m16n8k16.row.col.f32.f16.f16.f32 "
                    "{%0,%1,%2,%3}, {%4,%5,%6,%7}, {%8,%9}, {%0,%1,%2,%3};"
                    : "+f"(acc[nt][0]), "+f"(acc[nt][1]),
                      "+f"(acc[nt][2]), "+f"(acc[nt][3])
                    : "r"(af[0]), "r"(af[1]), "r"(af[2]), "r"(af[3]),
                      "r"(bf[nt][0]), "r"(bf[nt][1]));
            }
        }
        __syncthreads();
    }

    // store seq_fts as fp16
    {
        int r0 = rowBase + warp_m * 16 + group;
        #pragma unroll
        for (int nt = 0; nt < 8; nt++) {
            int cc = warp_n * 64 + nt * 8 + tig * 2;
            if (r0 < n)
                *(__half2*)(g_seqh + (size_t)r0 * DOUT + cc) =
                    __floats2half2_rn(acc[nt][0], acc[nt][1]);
            if (r0 + 8 < n)
                *(__half2*)(g_seqh + (size_t)(r0 + 8) * DOUT + cc) =
                    __floats2half2_rn(acc[nt][2], acc[nt][3]);
        }
    }

    // fused f1/f2 epilogue
    float awv[16], rwv[16];
    #pragma unroll
    for (int nt = 0; nt < 8; nt++) {
        int cc = warp_n * 64 + nt * 8 + tig * 2;
        float2 a2 = *(const float2*)(al_w + cc);
        float2 r2 = *(const float2*)(ar_w + cc);
        awv[nt * 2] = a2.x; awv[nt * 2 + 1] = a2.y;
        rwv[nt * 2] = r2.x; rwv[nt * 2 + 1] = r2.y;
    }

    float* smf = (float*)&As[0];        // repurpose: [0..63]=f1, [64..127]=f2
    float p1[2], p2[2];
    #pragma unroll
    for (int half = 0; half < 2; half++) {
        float s1 = 0.f, s2 = 0.f;
        #pragma unroll
        for (int nt = 0; nt < 8; nt++) {
            float v0 = acc[nt][half * 2];
            float v1 = acc[nt][half * 2 + 1];
            s1 += v0 * awv[nt * 2] + v1 * awv[nt * 2 + 1];
            s2 += v0 * rwv[nt * 2] + v1 * rwv[nt * 2 + 1];
        }
        s1 += __shfl_xor_sync(0xFFFFFFFFu, s1, 1);
        s1 += __shfl_xor_sync(0xFFFFFFFFu, s1, 2);
        s2 += __shfl_xor_sync(0xFFFFFFFFu, s2, 1);
        s2 += __shfl_xor_sync(0xFFFFFFFFu, s2, 2);
        p1[half] = s1; p2[half] = s2;
    }
    __syncthreads();
    if (warp_n == 0 && tig == 0) {
        #pragma unroll
        for (int half = 0; half < 2; half++) {
            int lr = warp_m * 16 + group + half * 8;
            smf[lr]      = p1[half];
            smf[64 + lr] = p2[half];
        }
    }
    __syncthreads();
    if (warp_n == 1 && tig == 0) {
        float ab = al_b[0], rb = ar_b[0];
        #pragma unroll
        for (int half = 0; half < 2; half++) {
            int lr = warp_m * 16 + group + half * 8;
            int gr = rowBase + lr;
            if (gr < n) {
                g_f1[gr] = smf[lr]      + p1[half] + ab;
                g_f2[gr] = smf[64 + lr] + p2[half] + rb;
            }
        }
    }
}

// ---------------------------------------------------------------------------
// spmm: CSR SpMM + fused softmax, one warp per node, lean x4 loop.
// 32-reg budget (launch_bounds 256,8) -> full occupancy.
// Exp dedup width 4: lane computes exp for slot (lane&3) via SEL from ca.
__global__ __launch_bounds__(256, 8) void k_spmm(const float* __restrict__ bias,
                                                 float* __restrict__ out, int n) {
    int gw   = (blockIdx.x * blockDim.x + threadIdx.x) >> 5;
    int lane = threadIdx.x & 31;
    if (gw >= n) return;
    int j0  = __ldg(&g_off[gw]);
    int end = __ldg(&g_cur[gw]);
    int j   = j0;

    float f1v = __ldg(&g_f1[gw]);
    float4 acc = make_float4(0.f, 0.f, 0.f, 0.f);
    float sslot = 0.0f;
    float stail = 0.0f;
    const uint2* lanebase = ((const uint2*)g_seqh) + lane;   // +c*32 per row

    // scalar peel to 16B alignment for int4 loads of g_ecol
    while (j < end && (j & 3)) {
        int c = __ldg(&g_ecol[j]);
        float x = f1v + __ldg(&g_f2[c]);
        float ev = __expf(x > 0.f ? x : ALPHA * x);
        stail += ev;
        uint2 u = __ldg(lanebase + ((size_t)c << 5));
        float2 a = __half22float2(*reinterpret_cast<__half2*>(&u.x));
        float2 b = __half22float2(*reinterpret_cast<__half2*>(&u.y));
        acc.x += ev * a.x; acc.y += ev * a.y;
        acc.z += ev * b.x; acc.w += ev * b.y;
        j++;
    }

    int slot = lane & 3;
    for (; j + 4 <= end; j += 4) {
        int4 ca = __ldg((const int4*)(g_ecol + j));
        // my slot's column via select (no extra load)
        int cmy = (slot == 0) ? ca.x : (slot == 1) ? ca.y : (slot == 2) ? ca.z : ca.w;
        float x = f1v + __ldg(&g_f2[cmy]);
        float emy = __expf(x > 0.f ? x : ALPHA * x);
        sslot += emy;
        float e0 = __shfl_sync(0xFFFFFFFFu, emy, 0, 4);
        float e1 = __shfl_sync(0xFFFFFFFFu, emy, 1, 4);
        float e2 = __shfl_sync(0xFFFFFFFFu, emy, 2, 4);
        float e3 = __shfl_sync(0xFFFFFFFFu, emy, 3, 4);
        uint2 u0 = __ldg(lanebase + ((size_t)ca.x << 5));
        uint2 u1 = __ldg(lanebase + ((size_t)ca.y << 5));
        uint2 u2 = __ldg(lanebase + ((size_t)ca.z << 5));
        uint2 u3 = __ldg(lanebase + ((size_t)ca.w << 5));
        float2 a0 = __half22float2(*reinterpret_cast<__half2*>(&u0.x));
        float2 b0 = __half22float2(*reinterpret_cast<__half2*>(&u0.y));
        float2 a1 = __half22float2(*reinterpret_cast<__half2*>(&u1.x));
        float2 b1 = __half22float2(*reinterpret_cast<__half2*>(&u1.y));
        float2 a2 = __half22float2(*reinterpret_cast<__half2*>(&u2.x));
        float2 b2 = __half22float2(*reinterpret_cast<__half2*>(&u2.y));
        float2 a3 = __half22float2(*reinterpret_cast<__half2*>(&u3.x));
        float2 b3 = __half22float2(*reinterpret_cast<__half2*>(&u3.y));
        acc.x += e0 * a0.x + e1 * a1.x + e2 * a2.x + e3 * a3.x;
        acc.y += e0 * a0.y + e1 * a1.y + e2 * a2.y + e3 * a3.y;
        acc.z += e0 * b0.x + e1 * b1.x + e2 * b2.x + e3 * b3.x;
        acc.w += e0 * b0.y + e1 * b1.y + e2 * b2.y + e3 * b3.y;
    }
    // tail
    for (; j < end; j++) {
        int c = __ldg(&g_ecol[j]);
        float x = f1v + __ldg(&g_f2[c]);
        float ev = __expf(x > 0.f ? x : ALPHA * x);
        stail += ev;
        uint2 u = __ldg(lanebase + ((size_t)c << 5));
        float2 a = __half22float2(*reinterpret_cast<__half2*>(&u.x));
        float2 b = __half22float2(*reinterpret_cast<__half2*>(&u.y));
        acc.x += ev * a.x; acc.y += ev * a.y;
        acc.z += ev * b.x; acc.w += ev * b.y;
    }

    // reduce slot partials within each 4-lane group (groups identical)
    float gsum = sslot;
    gsum += __shfl_xor_sync(0xFFFFFFFFu, gsum, 1);
    gsum += __shfl_xor_sync(0xFFFFFFFFu, gsum, 2);
    float ssum = gsum + stail;

    float inv = (end > j0) ? 1.0f / ssum : 0.0f;
    float4 b = ((const float4*)bias)[lane];
    acc.x = acc.x * inv + b.x;
    acc.y = acc.y * inv + b.y;
    acc.z = acc.z * inv + b.z;
    acc.w = acc.w * inv + b.w;
    ((float4*)(out + (size_t)gw * DOUT))[lane] = acc;
}

// ---------------------------------------------------------------------------
extern "C" void kernel_launch(void* const* d_in, const int* in_sizes, int n_in,
                              void* d_out, int out_size) {
    const float* feat = (const float*)d_in[0];
    const int*   row  = (const int*)  d_in[1];
    const int*   col  = (const int*)  d_in[2];
    const float* W    = (const float*)d_in[3];
    const float* al_w = (const float*)d_in[4];
    const float* al_b = (const float*)d_in[5];
    const float* ar_w = (const float*)d_in[6];
    const float* ar_b = (const float*)d_in[7];
    const float* bias = (const float*)d_in[8];
    float* out = (float*)d_out;

    int n = in_sizes[0] / DIN;   // 100000
    int e = in_sizes[1];         // 3200000
    int nblk = (n + 255) / 256;          // scan blocks (<= 512)
    int eblk = (e / 4 + 255) / 256;      // edge-pass blocks (3125)
    int GB   = (n + 63) / 64;            // gemm blocks (1563)

    k_combo1<<<WCONV_BLOCKS + eblk, 256>>>(W, row, e);            // wconv + edge1
    k_scan1<<<nblk, 256>>>(n);
    k_scan23<<<(n + 511) / 512, 512>>>(n, nblk);
    k_combo2<<<GB + eblk, 256>>>(feat, al_w, al_b, ar_w, ar_b,    // gemm + edge2
                                 row, col, n, e, GB);
    k_spmm<<<(n * 32 + 255) / 256, 256>>>(bias, out, n);
}

// round 14
// speedup vs baseline: 1.0349x; 1.0349x over previous
#include <cuda_runtime.h>
#include <cuda_fp16.h>
#include <math_constants.h>
#include <cstdint>

#define DIN  256
#define DOUT 128
#define NMAX 100000
#define EMAX 3200000
#define ALPHA 0.2f
#define WCONV_BLOCKS 128

// ---- scratch (static device globals; no allocation) ----
__device__ __half  g_seqh[(size_t)NMAX * DOUT]; // seq_fts (fp16 storage)
__device__ __half  g_Wh[DOUT * DIN];            // W transposed [n][k], fp16
__device__ float   g_f1[NMAX];
__device__ float   g_f2[NMAX];
__device__ int     g_cnt[NMAX];                 // zero at call entry (self-cleaning)
__device__ int     g_off[NMAX];
__device__ int     g_cur[NMAX];
__device__ int     g_bsum[512];
__device__ int     g_ecol[EMAX];

// ---------------------------------------------------------------------------
// combo1: blocks [0,128)   -> W transpose + fp16 convert
//         blocks [128,...) -> edge pass 1: per-row edge count (x4)
__global__ void k_combo1(const float* __restrict__ W,
                         const int* __restrict__ row, int e) {
    if (blockIdx.x < WCONV_BLOCKS) {
        int idx = blockIdx.x * blockDim.x + threadIdx.x;   // 0..32767
        int nn = idx >> 8;
        int kk = idx & 255;
        g_Wh[idx] = __float2half_rn(W[kk * DOUT + nn]);
    } else {
        int bi = blockIdx.x - WCONV_BLOCKS;
        int i = (bi * blockDim.x + threadIdx.x) * 4;
        if (i + 4 <= e) {
            int4 r4 = *(const int4*)(row + i);
            atomicAdd(&g_cnt[r4.x], 1);
            atomicAdd(&g_cnt[r4.y], 1);
            atomicAdd(&g_cnt[r4.z], 1);
            atomicAdd(&g_cnt[r4.w], 1);
        } else {
            for (int k = i; k < e; k++) atomicAdd(&g_cnt[row[k]], 1);
        }
    }
}

// ---------------------------------------------------------------------------
// scan1: block-local exclusive scan of g_cnt -> g_off; resets g_cnt.
__global__ void k_scan1(int n) {
    __shared__ int sh[256];
    int t = threadIdx.x;
    int i = blockIdx.x * 256 + t;
    int v = (i < n) ? g_cnt[i] : 0;
    sh[t] = v;
    __syncthreads();
    #pragma unroll
    for (int o = 1; o < 256; o <<= 1) {
        int x = (t >= o) ? sh[t - o] : 0;
        __syncthreads();
        sh[t] += x;
        __syncthreads();
    }
    if (i < n) { g_off[i] = sh[t] - v; g_cnt[i] = 0; }
    if (t == 255) g_bsum[blockIdx.x] = sh[255];
}

// scan23: every block redundantly scans the block sums, adds prefix.
__global__ void k_scan23(int n, int nblk) {
    __shared__ int sh[512];
    int t = threadIdx.x;
    int v = (t < nblk) ? g_bsum[t] : 0;
    sh[t] = v;
    __syncthreads();
    #pragma unroll
    for (int o = 1; o < 512; o <<= 1) {
        int x = (t >= o) ? sh[t - o] : 0;
        __syncthreads();
        sh[t] += x;
        __syncthreads();
    }
    int ex = sh[t] - v;
    __syncthreads();
    sh[t] = ex;
    __syncthreads();
    int i = blockIdx.x * 512 + t;
    if (i < n) {
        int o = g_off[i] + sh[i >> 8];
        g_off[i] = o;
        g_cur[i] = o;
    }
}

// ---------------------------------------------------------------------------
// combo2: blocks [0,GB)  -> fp16 HMMA GEMM (128x128 tile) + f1/f2 epilogue
//         blocks [GB,..) -> edge pass 2 (CSR scatter of col, x4)
#define HSTR 40
__global__ __launch_bounds__(256) void k_combo2(const float* __restrict__ A,
                                                const float* __restrict__ al_w,
                                                const float* __restrict__ al_b,
                                                const float* __restrict__ ar_w,
                                                const float* __restrict__ ar_b,
                                                const int* __restrict__ row,
                                                const int* __restrict__ col,
                                                int n, int e, int GB) {
    if (blockIdx.x >= GB) {
        int bi = blockIdx.x - GB;
        int i = (bi * blockDim.x + threadIdx.x) * 4;
        if (i + 4 <= e) {
            int4 r4 = *(const int4*)(row + i);
            int4 c4 = *(const int4*)(col + i);
            int p0 = atomicAdd(&g_cur[r4.x], 1);
            int p1 = atomicAdd(&g_cur[r4.y], 1);
            int p2 = atomicAdd(&g_cur[r4.z], 1);
            int p3 = atomicAdd(&g_cur[r4.w], 1);
            g_ecol[p0] = c4.x; g_ecol[p1] = c4.y;
            g_ecol[p2] = c4.z; g_ecol[p3] = c4.w;
        } else {
            for (int k = i; k < e; k++) {
                int p = atomicAdd(&g_cur[row[k]], 1);
                g_ecol[p] = col[k];
            }
        }
        return;
    }

    // ---------------- GEMM: 128 rows x 128 cols per block ----------------
    __shared__ __half As[128 * HSTR];   // [m][k]
    __shared__ __half Bs[128 * HSTR];   // [n][k]

    int tid  = threadIdx.x;
    int wid  = tid >> 5;
    int lane = tid & 31;
    int warp_m = wid & 3;
    int warp_n = wid >> 2;
    int group  = lane >> 2;
    int tig    = lane & 3;
    int rowBase = blockIdx.x * 128;

    float acc[2][8][4];
    #pragma unroll
    for (int mt = 0; mt < 2; mt++)
        #pragma unroll
        for (int nt = 0; nt < 8; nt++)
            #pragma unroll
            for (int q = 0; q < 4; q++) acc[mt][nt][q] = 0.0f;

    for (int k0 = 0; k0 < DIN; k0 += 32) {
        #pragma unroll
        for (int i = 0; i < 4; i++) {
            int idx = tid + 256 * i;
            int m   = idx >> 3;
            int q   = idx & 7;
            int gr  = rowBase + m;
            float4 v = make_float4(0.f, 0.f, 0.f, 0.f);
            if (gr < n) v = *(const float4*)(A + (size_t)gr * DIN + k0 + q * 4);
            __half2 h0 = __floats2half2_rn(v.x, v.y);
            __half2 h1 = __floats2half2_rn(v.z, v.w);
            uint2 u;
            u.x = *reinterpret_cast<uint32_t*>(&h0);
            u.y = *reinterpret_cast<uint32_t*>(&h1);
            *(uint2*)&As[m * HSTR + q * 4] = u;
        }
        #pragma unroll
        for (int i = 0; i < 2; i++) {
            int idx = tid + 256 * i;
            int nn  = idx >> 2;
            int q   = idx & 3;
            *(uint4*)&Bs[nn * HSTR + q * 8] =
                *(const uint4*)(g_Wh + nn * DIN + k0 + q * 8);
        }
        __syncthreads();

        #pragma unroll
        for (int ks = 0; ks < 2; ks++) {
            int kb = ks * 16;
            uint32_t af[2][4];
            #pragma unroll
            for (int mt = 0; mt < 2; mt++) {
                int m = warp_m * 32 + mt * 16 + group;
                const __half* pr0 = &As[m * HSTR + kb + tig * 2];
                const __half* pr1 = &As[(m + 8) * HSTR + kb + tig * 2];
                af[mt][0] = *(const uint32_t*)(pr0);
                af[mt][1] = *(const uint32_t*)(pr1);
                af[mt][2] = *(const uint32_t*)(pr0 + 8);
                af[mt][3] = *(const uint32_t*)(pr1 + 8);
            }
            uint32_t bf[8][2];
            #pragma unroll
            for (int nt = 0; nt < 8; nt++) {
                int nn = warp_n * 64 + nt * 8 + group;
                const __half* pb = &Bs[nn * HSTR + kb + tig * 2];
                bf[nt][0] = *(const uint32_t*)(pb);
                bf[nt][1] = *(const uint32_t*)(pb + 8);
            }
            #pragma unroll
            for (int mt = 0; mt < 2; mt++)
                #pragma unroll
                for (int nt = 0; nt < 8; nt++) {
                    asm volatile(
                        "mma.sync.aligned.m16n8k16.row.col.f32.f16.f16.f32 "
                        "{%0,%1,%2,%3}, {%4,%5,%6,%7}, {%8,%9}, {%0,%1,%2,%3};"
                        : "+f"(acc[mt][nt][0]), "+f"(acc[mt][nt][1]),
                          "+f"(acc[mt][nt][2]), "+f"(acc[mt][nt][3])
                        : "r"(af[mt][0]), "r"(af[mt][1]), "r"(af[mt][2]), "r"(af[mt][3]),
                          "r"(bf[nt][0]), "r"(bf[nt][1]));
                }
        }
        __syncthreads();
    }

    // store seq_fts as fp16
    #pragma unroll
    for (int mt = 0; mt < 2; mt++) {
        int r0 = rowBase + warp_m * 32 + mt * 16 + group;
        #pragma unroll
        for (int nt = 0; nt < 8; nt++) {
            int cc = warp_n * 64 + nt * 8 + tig * 2;
            if (r0 < n)
                *(__half2*)(g_seqh + (size_t)r0 * DOUT + cc) =
                    __floats2half2_rn(acc[mt][nt][0], acc[mt][nt][1]);
            if (r0 + 8 < n)
                *(__half2*)(g_seqh + (size_t)(r0 + 8) * DOUT + cc) =
                    __floats2half2_rn(acc[mt][nt][2], acc[mt][nt][3]);
        }
    }

    // fused f1/f2 epilogue
    float awv[16], rwv[16];
    #pragma unroll
    for (int nt = 0; nt < 8; nt++) {
        int cc = warp_n * 64 + nt * 8 + tig * 2;
        float2 a2 = *(const float2*)(al_w + cc);
        float2 r2 = *(const float2*)(ar_w + cc);
        awv[nt * 2] = a2.x; awv[nt * 2 + 1] = a2.y;
        rwv[nt * 2] = r2.x; rwv[nt * 2 + 1] = r2.y;
    }

    float* smf = (float*)&As[0];
    float p1[2][2], p2[2][2];
    #pragma unroll
    for (int mt = 0; mt < 2; mt++) {
        #pragma unroll
        for (int half = 0; half < 2; half++) {
            float s1 = 0.f, s2 = 0.f;
            #pragma unroll
            for (int nt = 0; nt < 8; nt++) {
                float v0 = acc[mt][nt][half * 2];
                float v1 = acc[mt][nt][half * 2 + 1];
                s1 += v0 * awv[nt * 2] + v1 * awv[nt * 2 + 1];
                s2 += v0 * rwv[nt * 2] + v1 * rwv[nt * 2 + 1];
            }
            s1 += __shfl_xor_sync(0xFFFFFFFFu, s1, 1);
            s1 += __shfl_xor_sync(0xFFFFFFFFu, s1, 2);
            s2 += __shfl_xor_sync(0xFFFFFFFFu, s2, 1);
            s2 += __shfl_xor_sync(0xFFFFFFFFu, s2, 2);
            p1[mt][half] = s1; p2[mt][half] = s2;
        }
    }
    __syncthreads();
    if (warp_n == 0 && tig == 0) {
        #pragma unroll
        for (int mt = 0; mt < 2; mt++)
            #pragma unroll
            for (int half = 0; half < 2; half++) {
                int lr = warp_m * 32 + mt * 16 + group + half * 8;
                smf[lr]       = p1[mt][half];
                smf[128 + lr] = p2[mt][half];
            }
    }
    __syncthreads();
    if (warp_n == 1 && tig == 0) {
        float ab = al_b[0], rb = ar_b[0];
        #pragma unroll
        for (int mt = 0; mt < 2; mt++)
            #pragma unroll
            for (int half = 0; half < 2; half++) {
                int lr = warp_m * 32 + mt * 16 + group + half * 8;
                int gr = rowBase + lr;
                if (gr < n) {
                    g_f1[gr] = smf[lr]       + p1[mt][half] + ab;
                    g_f2[gr] = smf[128 + lr] + p2[mt][half] + rb;
                }
            }
    }
}

// ---------------------------------------------------------------------------
// spmm: CSR SpMM + fused softmax, one warp per node, x4 loop with
// software-pipelined column prefetch (next int4 issued before current work).
__global__ __launch_bounds__(256) void k_spmm(const float* __restrict__ bias,
                                              float* __restrict__ out, int n) {
    int gw   = (blockIdx.x * blockDim.x + threadIdx.x) >> 5;
    int lane = threadIdx.x & 31;
    if (gw >= n) return;
    int j0  = __ldg(&g_off[gw]);
    int end = __ldg(&g_cur[gw]);
    int j   = j0;

    float f1v = __ldg(&g_f1[gw]);
    float4 acc = make_float4(0.f, 0.f, 0.f, 0.f);
    float ssum = 0.0f;
    const uint2* lanebase = ((const uint2*)g_seqh) + lane;   // +c*32 per row

    // scalar peel to 16B alignment for int4 loads of g_ecol
    while (j < end && (j & 3)) {
        int c = __ldg(&g_ecol[j]);
        float x = f1v + __ldg(&g_f2[c]);
        float ev = __expf(x > 0.f ? x : ALPHA * x);
        ssum += ev;
        uint2 u = __ldg(lanebase + ((size_t)c << 5));
        float2 a = __half22float2(*reinterpret_cast<__half2*>(&u.x));
        float2 b = __half22float2(*reinterpret_cast<__half2*>(&u.y));
        acc.x += ev * a.x; acc.y += ev * a.y;
        acc.z += ev * b.x; acc.w += ev * b.y;
        j++;
    }

    // pipelined x4 main loop: next iteration's columns prefetched
    int4 ca;
    if (j + 4 <= end) ca = __ldg((const int4*)(g_ecol + j));
    for (; j + 4 <= end; ) {
        int jn = j + 4;
        int4 can;
        if (jn + 4 <= end) can = __ldg((const int4*)(g_ecol + jn));  // prefetch
        // f2 + row gathers for CURRENT columns (already resolved)
        float w0 = __ldg(&g_f2[ca.x]), w1 = __ldg(&g_f2[ca.y]);
        float w2 = __ldg(&g_f2[ca.z]), w3 = __ldg(&g_f2[ca.w]);
        uint2 u0 = __ldg(lanebase + ((size_t)ca.x << 5));
        uint2 u1 = __ldg(lanebase + ((size_t)ca.y << 5));
        uint2 u2 = __ldg(lanebase + ((size_t)ca.z << 5));
        uint2 u3 = __ldg(lanebase + ((size_t)ca.w << 5));
        float x0 = f1v + w0, x1 = f1v + w1, x2 = f1v + w2, x3 = f1v + w3;
        float e0 = __expf(x0 > 0.f ? x0 : ALPHA * x0);
        float e1 = __expf(x1 > 0.f ? x1 : ALPHA * x1);
        float e2 = __expf(x2 > 0.f ? x2 : ALPHA * x2);
        float e3 = __expf(x3 > 0.f ? x3 : ALPHA * x3);
        ssum += (e0 + e1) + (e2 + e3);
        float2 a0 = __half22float2(*reinterpret_cast<__half2*>(&u0.x));
        float2 b0 = __half22float2(*reinterpret_cast<__half2*>(&u0.y));
        float2 a1 = __half22float2(*reinterpret_cast<__half2*>(&u1.x));
        float2 b1 = __half22float2(*reinterpret_cast<__half2*>(&u1.y));
        float2 a2 = __half22float2(*reinterpret_cast<__half2*>(&u2.x));
        float2 b2 = __half22float2(*reinterpret_cast<__half2*>(&u2.y));
        float2 a3 = __half22float2(*reinterpret_cast<__half2*>(&u3.x));
        float2 b3 = __half22float2(*reinterpret_cast<__half2*>(&u3.y));
        acc.x += e0 * a0.x + e1 * a1.x + e2 * a2.x + e3 * a3.x;
        acc.y += e0 * a0.y + e1 * a1.y + e2 * a2.y + e3 * a3.y;
        acc.z += e0 * b0.x + e1 * b1.x + e2 * b2.x + e3 * b3.x;
        acc.w += e0 * b0.y + e1 * b1.y + e2 * b2.y + e3 * b3.y;
        j = jn;
        ca = can;
    }
    // tail
    for (; j < end; j++) {
        int c = __ldg(&g_ecol[j]);
        float x = f1v + __ldg(&g_f2[c]);
        float ev = __expf(x > 0.f ? x : ALPHA * x);
        ssum += ev;
        uint2 u = __ldg(lanebase + ((size_t)c << 5));
        float2 a = __half22float2(*reinterpret_cast<__half2*>(&u.x));
        float2 b = __half22float2(*reinterpret_cast<__half2*>(&u.y));
        acc.x += ev * a.x; acc.y += ev * a.y;
        acc.z += ev * b.x; acc.w += ev * b.y;
    }

    float inv = (end > j0) ? 1.0f / ssum : 0.0f;
    float4 b = ((const float4*)bias)[lane];
    acc.x = acc.x * inv + b.x;
    acc.y = acc.y * inv + b.y;
    acc.z = acc.z * inv + b.z;
    acc.w = acc.w * inv + b.w;
    ((float4*)(out + (size_t)gw * DOUT))[lane] = acc;
}

// ---------------------------------------------------------------------------
extern "C" void kernel_launch(void* const* d_in, const int* in_sizes, int n_in,
                              void* d_out, int out_size) {
    const float* feat = (const float*)d_in[0];
    const int*   row  = (const int*)  d_in[1];
    const int*   col  = (const int*)  d_in[2];
    const float* W    = (const float*)d_in[3];
    const float* al_w = (const float*)d_in[4];
    const float* al_b = (const float*)d_in[5];
    const float* ar_w = (const float*)d_in[6];
    const float* ar_b = (const float*)d_in[7];
    const float* bias = (const float*)d_in[8];
    float* out = (float*)d_out;

    int n = in_sizes[0] / DIN;   // 100000
    int e = in_sizes[1];         // 3200000
    int nblk = (n + 255) / 256;          // scan blocks (<= 512)
    int eblk = (e / 4 + 255) / 256;      // edge-pass blocks (3125)
    int GB   = (n + 127) / 128;          // gemm blocks (782)

    k_combo1<<<WCONV_BLOCKS + eblk, 256>>>(W, row, e);            // wconv + edge1
    k_scan1<<<nblk, 256>>>(n);
    k_scan23<<<(n + 511) / 512, 512>>>(n, nblk);
    k_combo2<<<GB + eblk, 256>>>(feat, al_w, al_b, ar_w, ar_b,    // gemm + edge2
                                 row, col, n, e, GB);
    k_spmm<<<(n * 32 + 255) / 256, 256>>>(bias, out, n);
}